// round 11
// baseline (speedup 1.0000x reference)
#include <cuda_runtime.h>
#include <math.h>

#define D 64
#define EPS_M 1e-7f
#define N_MAX 100001
#define NBG 8           // nodes per warp in GEMM kernel

__device__ float g_WT[D * D];           // g_WT[d*64 + c] = W[c][d]
__device__ int   g_off[N_MAX + 1];      // CSR offsets into sorted dst
__device__ float g_feat[(N_MAX - 1) * D]; // intermediate features (25.6 MB)

// ---- pre-kernel: CSR offsets + W transpose ----
__global__ void prep_kernel(const int* __restrict__ dst,
                            const float* __restrict__ W,
                            int n_nodes, int n_edges)
{
    const int i = blockIdx.x * blockDim.x + threadIdx.x;
    if (i < D * D) {
        int r = i >> 6, c = i & 63;       // W[r][c]
        g_WT[c * D + r] = W[i];
    }
    if (i <= n_nodes) {
        if (i == n_nodes) { g_off[i] = n_edges; }
        else {
            int lo = 0, hi = n_edges;
            while (lo < hi) { int mid = (lo + hi) >> 1; if (dst[mid] < i) lo = mid + 1; else hi = mid; }
            g_off[i] = lo;
        }
    }
}

// eps folded out: accumulate over r = relu(a+b); agg = sme/se + eps (exact)
__device__ __forceinline__ void edge_step(const float4 a, const float4 b,
                                          float4& se, float4& sme)
{
    const float r0 = fmaxf(a.x + b.x, 0.f);
    const float r1 = fmaxf(a.y + b.y, 0.f);
    const float r2 = fmaxf(a.z + b.z, 0.f);
    const float r3 = fmaxf(a.w + b.w, 0.f);
    const float p0 = __expf(r0), p1 = __expf(r1);
    const float p2 = __expf(r2), p3 = __expf(r3);
    se.x += p0; se.y += p1; se.z += p2; se.w += p3;
    sme.x = fmaf(r0, p0, sme.x); sme.y = fmaf(r1, p1, sme.y);
    sme.z = fmaf(r2, p2, sme.z); sme.w = fmaf(r3, p3, sme.w);
}

// ---- kernel 1: gather + softmax + MessageNorm -> g_feat (no smem) ----
__global__ void __launch_bounds__(256) edge_kernel(
    const float* __restrict__ nf,     // [N, 64]
    const float* __restrict__ ef,     // [E, 64]
    const float* __restrict__ scale,  // [1]
    const int*   __restrict__ src,    // [E]
    int n_nodes)
{
    const int lane = threadIdx.x & 31;
    const int eo   = lane >> 4;           // half-warp edge offset (0/1)
    const int c4   = (lane & 15) * 4;     // channels c4..c4+3
    const int gw   = (blockIdx.x * blockDim.x + threadIdx.x) >> 5;
    const int nwarps = (gridDim.x * blockDim.x) >> 5;
    const float sc = scale[0];

    for (int node = gw; node < n_nodes; node += nwarps) {
        const float4 h4 = *(const float4*)(nf + (size_t)node * D + c4);
        const int s    = g_off[node];
        const int eend = g_off[node + 1];

        float4 se  = make_float4(0.f, 0.f, 0.f, 0.f);
        float4 sme = make_float4(0.f, 0.f, 0.f, 0.f);
        int e = s + eo;
        // R5-validated: 2 edges per half-warp per iter = 4 edges/warp in flight
        for (; e + 2 < eend; e += 4) {
            const int sp0 = __ldg(&src[e]);
            const int sp1 = __ldg(&src[e + 2]);
            const float4 b0 = __ldcs((const float4*)(ef + (size_t)e * D + c4));
            const float4 b1 = __ldcs((const float4*)(ef + (size_t)(e + 2) * D + c4));
            const float4 a0 = *(const float4*)(nf + sp0 * D + c4);
            const float4 a1 = *(const float4*)(nf + sp1 * D + c4);
            edge_step(a0, b0, se, sme);
            edge_step(a1, b1, se, sme);
        }
        if (e < eend) {
            const int sp0 = __ldg(&src[e]);
            const float4 b0 = __ldcs((const float4*)(ef + (size_t)e * D + c4));
            const float4 a0 = *(const float4*)(nf + sp0 * D + c4);
            edge_step(a0, b0, se, sme);
        }
        // combine the two edge-halves (lane q <-> lane q+16)
        se.x += __shfl_xor_sync(0xffffffffu, se.x, 16);
        se.y += __shfl_xor_sync(0xffffffffu, se.y, 16);
        se.z += __shfl_xor_sync(0xffffffffu, se.z, 16);
        se.w += __shfl_xor_sync(0xffffffffu, se.w, 16);
        sme.x += __shfl_xor_sync(0xffffffffu, sme.x, 16);
        sme.y += __shfl_xor_sync(0xffffffffu, sme.y, 16);
        sme.z += __shfl_xor_sync(0xffffffffu, sme.z, 16);
        sme.w += __shfl_xor_sync(0xffffffffu, sme.w, 16);

        float4 agg;   // eps folded back in (exact)
        agg.x = (se.x > 0.f) ? (sme.x / se.x + EPS_M) : 0.f;
        agg.y = (se.y > 0.f) ? (sme.y / se.y + EPS_M) : 0.f;
        agg.z = (se.z > 0.f) ? (sme.z / se.z + EPS_M) : 0.f;
        agg.w = (se.w > 0.f) ? (sme.w / se.w + EPS_M) : 0.f;

        float a2s = fmaf(agg.x, agg.x, fmaf(agg.y, agg.y, fmaf(agg.z, agg.z, agg.w * agg.w)));
        float h2s = fmaf(h4.x, h4.x, fmaf(h4.y, h4.y, fmaf(h4.z, h4.z, h4.w * h4.w)));
        #pragma unroll
        for (int o = 8; o > 0; o >>= 1) {
            a2s += __shfl_xor_sync(0xffffffffu, a2s, o);
            h2s += __shfl_xor_sync(0xffffffffu, h2s, o);
        }

        const float coef = (sqrtf(h2s) * sc) / fmaxf(sqrtf(a2s), 1e-12f);
        if (lane < 16) {
            float4 f;
            f.x = fmaf(agg.x, coef, h4.x);
            f.y = fmaf(agg.y, coef, h4.y);
            f.z = fmaf(agg.z, coef, h4.z);
            f.w = fmaf(agg.w, coef, h4.w);
            *(float4*)(g_feat + (size_t)node * D + c4) = f;   // 16 lanes x 16B
        }
    }
}

// ---- kernel 2: out = feat @ WT + b (memory-bound mini-GEMM) ----
__global__ void __launch_bounds__(256) gemm_kernel(
    const float* __restrict__ bvec,   // [64]
    float*       __restrict__ out,    // [N, 64]
    int n_nodes)
{
    __shared__ float sWT[D * D];            // 16 KB
    __shared__ float s_feat[8][NBG][D];     // 16 KB

    const int lane = threadIdx.x & 31;
    const int wim  = threadIdx.x >> 5;
    const int c2   = lane * 2;
    const int gw   = (blockIdx.x * blockDim.x + threadIdx.x) >> 5;
    const int nwarps = (gridDim.x * blockDim.x) >> 5;

    {   // stage WT once per block
        const float4* s4 = (const float4*)g_WT;
        float4* d4 = (float4*)sWT;
        for (int i = threadIdx.x; i < (D * D) / 4; i += 256) d4[i] = s4[i];
    }
    __syncthreads();

    const float2 bv = *(const float2*)(bvec + c2);
    const int nchunks = (n_nodes + NBG - 1) / NBG;

    for (int chunk = gw; chunk < nchunks; chunk += nwarps) {
        const int base = chunk * NBG;
        const int nvalid = min(NBG, n_nodes - base);

        // cooperative load of NBG feat rows (coalesced float4)
        for (int idx = lane; idx < nvalid * (D / 4); idx += 32) {
            const int r = idx >> 4;           // row in chunk
            const int c = idx & 15;           // float4 col
            ((float4*)&s_feat[wim][r][0])[c] =
                *(const float4*)(g_feat + (size_t)(base + r) * D + c * 4);
        }
        __syncwarp();

        float2 acc[NBG];
        #pragma unroll
        for (int i = 0; i < NBG; ++i) acc[i] = bv;

        #pragma unroll
        for (int d4 = 0; d4 < D; d4 += 4) {
            const float2 w0 = *(const float2*)(sWT + (d4 + 0) * D + c2);
            const float2 w1 = *(const float2*)(sWT + (d4 + 1) * D + c2);
            const float2 w2 = *(const float2*)(sWT + (d4 + 2) * D + c2);
            const float2 w3 = *(const float2*)(sWT + (d4 + 3) * D + c2);
            #pragma unroll
            for (int i = 0; i < NBG; ++i) {
                const float4 f = *(const float4*)&s_feat[wim][i][d4];  // broadcast
                acc[i].x = fmaf(f.x, w0.x, acc[i].x); acc[i].y = fmaf(f.x, w0.y, acc[i].y);
                acc[i].x = fmaf(f.y, w1.x, acc[i].x); acc[i].y = fmaf(f.y, w1.y, acc[i].y);
                acc[i].x = fmaf(f.z, w2.x, acc[i].x); acc[i].y = fmaf(f.z, w2.y, acc[i].y);
                acc[i].x = fmaf(f.w, w3.x, acc[i].x); acc[i].y = fmaf(f.w, w3.y, acc[i].y);
            }
        }
        #pragma unroll
        for (int i = 0; i < NBG; ++i)
            if (i < nvalid)
                *(float2*)(out + (size_t)(base + i) * D + c2) = acc[i];
        __syncwarp();
    }
}

extern "C" void kernel_launch(void* const* d_in, const int* in_sizes, int n_in,
                              void* d_out, int out_size)
{
    const float* nf    = (const float*)d_in[0];
    const float* ef    = (const float*)d_in[1];
    const float* W     = (const float*)d_in[2];
    const float* bvec  = (const float*)d_in[3];
    const float* scale = (const float*)d_in[4];
    const int*   src   = (const int*)d_in[5];
    const int*   dst   = (const int*)d_in[6];
    float* out = (float*)d_out;

    const int n_nodes = in_sizes[0] / D;
    const int n_edges = in_sizes[5];

    prep_kernel<<<(n_nodes + 256) / 256, 256>>>(dst, W, n_nodes, n_edges);
    edge_kernel<<<1184, 256>>>(nf, ef, scale, src, n_nodes);
    gemm_kernel<<<592, 256>>>(bvec, out, n_nodes);
}

// round 12
// speedup vs baseline: 1.2003x; 1.2003x over previous
#include <cuda_runtime.h>
#include <math.h>

#define D 64
#define EPS_M 1e-7f
#define N_MAX 100001
#define NB 4            // nodes per warp-chunk (register-tiled GEMM)

__device__ float g_WT[D * D];       // g_WT[d*64 + c] = W[c][d]
__device__ int   g_off[N_MAX + 3];  // CSR offsets (padded for int4 loads)

// ---- single pre-kernel: CSR offsets + W transpose ----
__global__ void prep_kernel(const int* __restrict__ dst,
                            const float* __restrict__ W,
                            int n_nodes, int n_edges)
{
    const int i = blockIdx.x * blockDim.x + threadIdx.x;
    if (i < D * D) {
        int r = i >> 6, c = i & 63;       // W[r][c]
        g_WT[c * D + r] = W[i];
    }
    if (i <= n_nodes + 2) {
        if (i >= n_nodes) { g_off[i] = n_edges; }
        else {
            int lo = 0, hi = n_edges;
            while (lo < hi) { int mid = (lo + hi) >> 1; if (dst[mid] < i) lo = mid + 1; else hi = mid; }
            g_off[i] = lo;
        }
    }
}

// eps folded out: accumulate over r = relu(a+b); agg = sme/se + eps (exact)
__device__ __forceinline__ void edge_step(const float4 a, const float4 b,
                                          float4& se, float4& sme)
{
    const float r0 = fmaxf(a.x + b.x, 0.f);
    const float r1 = fmaxf(a.y + b.y, 0.f);
    const float r2 = fmaxf(a.z + b.z, 0.f);
    const float r3 = fmaxf(a.w + b.w, 0.f);
    const float p0 = __expf(r0), p1 = __expf(r1);
    const float p2 = __expf(r2), p3 = __expf(r3);
    se.x += p0; se.y += p1; se.z += p2; se.w += p3;
    sme.x = fmaf(r0, p0, sme.x); sme.y = fmaf(r1, p1, sme.y);
    sme.z = fmaf(r2, p2, sme.z); sme.w = fmaf(r3, p3, sme.w);
}

// ---- main kernel: warp handles NB consecutive nodes, then 4x64 mini-GEMM ----
__global__ void __launch_bounds__(256) genconv_kernel(
    const float* __restrict__ nf,     // [N, 64]
    const float* __restrict__ ef,     // [E, 64]
    const float* __restrict__ bvec,   // [64]
    const float* __restrict__ scale,  // [1]
    const int*   __restrict__ src,    // [E]
    float*       __restrict__ out,    // [N, 64]
    int n_nodes)
{
    __shared__ float sWT[D * D];          // 16 KB
    __shared__ float s_feat[8][NB][D];    // 8 KB

    const int lane = threadIdx.x & 31;
    const int wim  = threadIdx.x >> 5;
    const int eo   = lane >> 4;           // edge offset (0/1): half-warp per edge
    const int c4   = (lane & 15) * 4;     // channels c4..c4+3 in edge loop
    const int c2   = lane * 2;            // channels c2,c2+1 in GEMM
    const int gw   = (blockIdx.x * blockDim.x + threadIdx.x) >> 5;
    const int nwarps = (gridDim.x * blockDim.x) >> 5;

    {   // stage WT once per block
        const float4* s4 = (const float4*)g_WT;
        float4* d4 = (float4*)sWT;
        for (int i = threadIdx.x; i < (D * D) / 4; i += 256) d4[i] = s4[i];
    }
    __syncthreads();

    const float sc = scale[0];
    const float2 bv = *(const float2*)(bvec + c2);
    const int nchunks = (n_nodes + NB - 1) / NB;

    for (int chunk = gw; chunk < nchunks; chunk += nwarps) {
        const int base = chunk * NB;
        // one vector load for offsets base..base+3, +1 scalar for base+4
        const int4 off4 = *(const int4*)(g_off + base);
        const int off5  = g_off[base + 4];
        int offs[NB + 1] = { off4.x, off4.y, off4.z, off4.w, off5 };

        #pragma unroll
        for (int i = 0; i < NB; ++i) {
            const int node = base + i;
            float4 se  = make_float4(0.f, 0.f, 0.f, 0.f);
            float4 sme = make_float4(0.f, 0.f, 0.f, 0.f);
            float4 h4  = make_float4(0.f, 0.f, 0.f, 0.f);

            if (node < n_nodes) {
                h4 = *(const float4*)(nf + (size_t)node * D + c4);
                const int s    = offs[i];
                const int eend = offs[i + 1];
                int e = s + eo;
                // strength-reduced pointers (IADD-only per iteration)
                const int*   ps = src + e;
                const float* pe = ef + (size_t)e * D + c4;
                // pipelined: 2 edges per half-warp per iter = 4 edges/warp in flight
                for (; e + 2 < eend; e += 4, ps += 4, pe += 4 * D) {
                    const int sp0 = __ldg(ps);
                    const int sp1 = __ldg(ps + 2);
                    const float4 b0 = __ldcs((const float4*)pe);
                    const float4 b1 = __ldcs((const float4*)(pe + 2 * D));
                    const float4 a0 = *(const float4*)(nf + sp0 * D + c4);
                    const float4 a1 = *(const float4*)(nf + sp1 * D + c4);
                    edge_step(a0, b0, se, sme);
                    edge_step(a1, b1, se, sme);
                }
                if (e < eend) {
                    const int sp0 = __ldg(ps);
                    const float4 b0 = __ldcs((const float4*)pe);
                    const float4 a0 = *(const float4*)(nf + sp0 * D + c4);
                    edge_step(a0, b0, se, sme);
                }
            }
            // combine the two edge-halves (lane q <-> lane q+16)
            se.x += __shfl_xor_sync(0xffffffffu, se.x, 16);
            se.y += __shfl_xor_sync(0xffffffffu, se.y, 16);
            se.z += __shfl_xor_sync(0xffffffffu, se.z, 16);
            se.w += __shfl_xor_sync(0xffffffffu, se.w, 16);
            sme.x += __shfl_xor_sync(0xffffffffu, sme.x, 16);
            sme.y += __shfl_xor_sync(0xffffffffu, sme.y, 16);
            sme.z += __shfl_xor_sync(0xffffffffu, sme.z, 16);
            sme.w += __shfl_xor_sync(0xffffffffu, sme.w, 16);

            // fast division; eps folded back in (exact)
            float4 agg;
            agg.x = (se.x > 0.f) ? (__fdividef(sme.x, se.x) + EPS_M) : 0.f;
            agg.y = (se.y > 0.f) ? (__fdividef(sme.y, se.y) + EPS_M) : 0.f;
            agg.z = (se.z > 0.f) ? (__fdividef(sme.z, se.z) + EPS_M) : 0.f;
            agg.w = (se.w > 0.f) ? (__fdividef(sme.w, se.w) + EPS_M) : 0.f;

            float a2s = fmaf(agg.x, agg.x, fmaf(agg.y, agg.y, fmaf(agg.z, agg.z, agg.w * agg.w)));
            float h2s = fmaf(h4.x, h4.x, fmaf(h4.y, h4.y, fmaf(h4.z, h4.z, h4.w * h4.w)));
            #pragma unroll
            for (int o = 8; o > 0; o >>= 1) {
                a2s += __shfl_xor_sync(0xffffffffu, a2s, o);
                h2s += __shfl_xor_sync(0xffffffffu, h2s, o);
            }

            // coef = ||h|| * sc / max(||agg||, 1e-12)  via rsqrt (1 MUFU)
            const float coef = sqrtf(h2s) * sc * rsqrtf(fmaxf(a2s, 1e-24f));
            if (lane < 16) {
                float4 f;
                f.x = fmaf(agg.x, coef, h4.x);
                f.y = fmaf(agg.y, coef, h4.y);
                f.z = fmaf(agg.z, coef, h4.z);
                f.w = fmaf(agg.w, coef, h4.w);
                *(float4*)&s_feat[wim][i][c4] = f;
            }
        }
        __syncwarp();

        // mini-GEMM: out[base..base+3][c2,c2+1] = b + feat @ WT
        float2 acc[NB];
        #pragma unroll
        for (int i = 0; i < NB; ++i) acc[i] = bv;

        #pragma unroll
        for (int d4 = 0; d4 < D; d4 += 4) {
            const float2 w0 = *(const float2*)(sWT + (d4 + 0) * D + c2);
            const float2 w1 = *(const float2*)(sWT + (d4 + 1) * D + c2);
            const float2 w2 = *(const float2*)(sWT + (d4 + 2) * D + c2);
            const float2 w3 = *(const float2*)(sWT + (d4 + 3) * D + c2);
            #pragma unroll
            for (int i = 0; i < NB; ++i) {
                const float4 f = *(const float4*)&s_feat[wim][i][d4];  // broadcast
                acc[i].x = fmaf(f.x, w0.x, acc[i].x); acc[i].y = fmaf(f.x, w0.y, acc[i].y);
                acc[i].x = fmaf(f.y, w1.x, acc[i].x); acc[i].y = fmaf(f.y, w1.y, acc[i].y);
                acc[i].x = fmaf(f.z, w2.x, acc[i].x); acc[i].y = fmaf(f.z, w2.y, acc[i].y);
                acc[i].x = fmaf(f.w, w3.x, acc[i].x); acc[i].y = fmaf(f.w, w3.y, acc[i].y);
            }
        }
        #pragma unroll
        for (int i = 0; i < NB; ++i)
            if (base + i < n_nodes)
                *(float2*)(out + (size_t)(base + i) * D + c2) = acc[i];
        __syncwarp();   // protect s_feat WAR for next chunk
    }
}

extern "C" void kernel_launch(void* const* d_in, const int* in_sizes, int n_in,
                              void* d_out, int out_size)
{
    const float* nf    = (const float*)d_in[0];
    const float* ef    = (const float*)d_in[1];
    const float* W     = (const float*)d_in[2];
    const float* bvec  = (const float*)d_in[3];
    const float* scale = (const float*)d_in[4];
    const int*   src   = (const int*)d_in[5];
    const int*   dst   = (const int*)d_in[6];
    float* out = (float*)d_out;

    const int n_nodes = in_sizes[0] / D;
    const int n_edges = in_sizes[5];

    prep_kernel<<<(n_nodes + 3 + 256) / 256, 256>>>(dst, W, n_nodes, n_edges);
    genconv_kernel<<<1480, 256>>>(nf, ef, bvec, scale, src, out, n_nodes);
}

// round 13
// speedup vs baseline: 1.4833x; 1.2357x over previous
#include <cuda_runtime.h>
#include <math.h>

#define D 64
#define EPS_M 1e-7f
#define N_MAX 100001
#define NB 4            // nodes per warp-chunk (register-tiled GEMM)

__device__ float g_WT[D * D];       // g_WT[d*64 + c] = W[c][d]
__device__ int   g_off[N_MAX + 1];  // CSR offsets into sorted dst

// ---- pre-kernel: scatter-based CSR offsets + W transpose ----
// thread e writes g_off[n] = e+1 for all n in (dst[e], dst[e+1]];
// thread 0 also writes g_off[0..dst[0]] = 0. No dependent load chains.
__global__ void prep_kernel(const int* __restrict__ dst,
                            const float* __restrict__ W,
                            int n_nodes, int n_edges)
{
    const int i = blockIdx.x * blockDim.x + threadIdx.x;
    if (i < D * D) {
        int r = i >> 6, c = i & 63;       // W[r][c]
        g_WT[c * D + r] = W[i];
    }
    if (i < n_edges) {
        const int d0 = __ldg(&dst[i]);
        const int d1 = (i + 1 < n_edges) ? __ldg(&dst[i + 1]) : n_nodes;
        for (int n = d0 + 1; n <= d1; ++n) g_off[n] = i + 1;
        if (i == 0)
            for (int n = 0; n <= d0; ++n) g_off[n] = 0;
    }
}

__device__ __forceinline__ void edge_step(const float4 a, const float4 b,
                                          float4& se, float4& sme)
{
    const float m0 = fmaxf(a.x + b.x, 0.f) + EPS_M;
    const float m1 = fmaxf(a.y + b.y, 0.f) + EPS_M;
    const float m2 = fmaxf(a.z + b.z, 0.f) + EPS_M;
    const float m3 = fmaxf(a.w + b.w, 0.f) + EPS_M;
    const float p0 = __expf(m0), p1 = __expf(m1);
    const float p2 = __expf(m2), p3 = __expf(m3);
    se.x += p0; se.y += p1; se.z += p2; se.w += p3;
    sme.x = fmaf(m0, p0, sme.x); sme.y = fmaf(m1, p1, sme.y);
    sme.z = fmaf(m2, p2, sme.z); sme.w = fmaf(m3, p3, sme.w);
}

// ---- main kernel: warp handles NB consecutive nodes, then 4x64 mini-GEMM ----
// (byte-identical to the R5 kernel that measured 102.2us)
__global__ void __launch_bounds__(256) genconv_kernel(
    const float* __restrict__ nf,     // [N, 64]
    const float* __restrict__ ef,     // [E, 64]
    const float* __restrict__ bvec,   // [64]
    const float* __restrict__ scale,  // [1]
    const int*   __restrict__ src,    // [E]
    float*       __restrict__ out,    // [N, 64]
    int n_nodes)
{
    __shared__ float sWT[D * D];          // 16 KB
    __shared__ float s_feat[8][NB][D];    // 8 KB

    const int lane = threadIdx.x & 31;
    const int wim  = threadIdx.x >> 5;
    const int q    = lane & 15;           // channel-quad index (0..15)
    const int eo   = lane >> 4;           // edge offset (0/1): half-warp per edge
    const int c4   = q * 4;               // channels c4..c4+3 in edge loop
    const int c2   = lane * 2;            // channels c2,c2+1 in GEMM
    const int gw   = (blockIdx.x * blockDim.x + threadIdx.x) >> 5;
    const int nwarps = (gridDim.x * blockDim.x) >> 5;

    {   // stage WT once per block
        const float4* s4 = (const float4*)g_WT;
        float4* d4 = (float4*)sWT;
        for (int i = threadIdx.x; i < (D * D) / 4; i += 256) d4[i] = s4[i];
    }
    __syncthreads();

    const float sc = scale[0];
    const float2 bv = *(const float2*)(bvec + c2);
    const int nchunks = (n_nodes + NB - 1) / NB;

    for (int chunk = gw; chunk < nchunks; chunk += nwarps) {
        const int base = chunk * NB;

        #pragma unroll
        for (int i = 0; i < NB; ++i) {
            const int node = base + i;
            float4 se  = make_float4(0.f, 0.f, 0.f, 0.f);
            float4 sme = make_float4(0.f, 0.f, 0.f, 0.f);
            float4 h4  = make_float4(0.f, 0.f, 0.f, 0.f);

            if (node < n_nodes) {
                h4 = *(const float4*)(nf + node * D + c4);
                const int s    = g_off[node];
                const int eend = g_off[node + 1];
                int e = s + eo;
                // pipelined: 2 edges per half-warp per iter = 4 edges/warp in flight
                for (; e + 2 < eend; e += 4) {
                    const int sp0 = __ldg(&src[e]);
                    const int sp1 = __ldg(&src[e + 2]);
                    const float4 b0 = __ldcs((const float4*)(ef + (size_t)e * D + c4));
                    const float4 b1 = __ldcs((const float4*)(ef + (size_t)(e + 2) * D + c4));
                    const float4 a0 = *(const float4*)(nf + sp0 * D + c4);
                    const float4 a1 = *(const float4*)(nf + sp1 * D + c4);
                    edge_step(a0, b0, se, sme);
                    edge_step(a1, b1, se, sme);
                }
                if (e < eend) {
                    const int sp0 = __ldg(&src[e]);
                    const float4 b0 = __ldcs((const float4*)(ef + (size_t)e * D + c4));
                    const float4 a0 = *(const float4*)(nf + sp0 * D + c4);
                    edge_step(a0, b0, se, sme);
                }
            }
            // combine the two edge-halves (lane q <-> lane q+16)
            se.x += __shfl_xor_sync(0xffffffffu, se.x, 16);
            se.y += __shfl_xor_sync(0xffffffffu, se.y, 16);
            se.z += __shfl_xor_sync(0xffffffffu, se.z, 16);
            se.w += __shfl_xor_sync(0xffffffffu, se.w, 16);
            sme.x += __shfl_xor_sync(0xffffffffu, sme.x, 16);
            sme.y += __shfl_xor_sync(0xffffffffu, sme.y, 16);
            sme.z += __shfl_xor_sync(0xffffffffu, sme.z, 16);
            sme.w += __shfl_xor_sync(0xffffffffu, sme.w, 16);

            float4 agg;
            agg.x = (se.x > 0.f) ? (sme.x / se.x) : 0.f;
            agg.y = (se.y > 0.f) ? (sme.y / se.y) : 0.f;
            agg.z = (se.z > 0.f) ? (sme.z / se.z) : 0.f;
            agg.w = (se.w > 0.f) ? (sme.w / se.w) : 0.f;

            float a2s = fmaf(agg.x, agg.x, fmaf(agg.y, agg.y, fmaf(agg.z, agg.z, agg.w * agg.w)));
            float h2s = fmaf(h4.x, h4.x, fmaf(h4.y, h4.y, fmaf(h4.z, h4.z, h4.w * h4.w)));
            #pragma unroll
            for (int o = 8; o > 0; o >>= 1) {
                a2s += __shfl_xor_sync(0xffffffffu, a2s, o);
                h2s += __shfl_xor_sync(0xffffffffu, h2s, o);
            }

            const float coef = (sqrtf(h2s) * sc) / fmaxf(sqrtf(a2s), 1e-12f);
            if (lane < 16) {
                float4 f;
                f.x = fmaf(agg.x, coef, h4.x);
                f.y = fmaf(agg.y, coef, h4.y);
                f.z = fmaf(agg.z, coef, h4.z);
                f.w = fmaf(agg.w, coef, h4.w);
                *(float4*)&s_feat[wim][i][c4] = f;
            }
        }
        __syncwarp();

        // mini-GEMM: out[base..base+3][c2,c2+1] = b + feat @ WT
        float2 acc[NB];
        #pragma unroll
        for (int i = 0; i < NB; ++i) acc[i] = bv;

        #pragma unroll
        for (int d4 = 0; d4 < D; d4 += 4) {
            const float2 w0 = *(const float2*)(sWT + (d4 + 0) * D + c2);
            const float2 w1 = *(const float2*)(sWT + (d4 + 1) * D + c2);
            const float2 w2 = *(const float2*)(sWT + (d4 + 2) * D + c2);
            const float2 w3 = *(const float2*)(sWT + (d4 + 3) * D + c2);
            #pragma unroll
            for (int i = 0; i < NB; ++i) {
                const float4 f = *(const float4*)&s_feat[wim][i][d4];  // broadcast
                acc[i].x = fmaf(f.x, w0.x, acc[i].x); acc[i].y = fmaf(f.x, w0.y, acc[i].y);
                acc[i].x = fmaf(f.y, w1.x, acc[i].x); acc[i].y = fmaf(f.y, w1.y, acc[i].y);
                acc[i].x = fmaf(f.z, w2.x, acc[i].x); acc[i].y = fmaf(f.z, w2.y, acc[i].y);
                acc[i].x = fmaf(f.w, w3.x, acc[i].x); acc[i].y = fmaf(f.w, w3.y, acc[i].y);
            }
        }
        #pragma unroll
        for (int i = 0; i < NB; ++i)
            if (base + i < n_nodes)
                *(float2*)(out + (size_t)(base + i) * D + c2) = acc[i];
        __syncwarp();   // protect s_feat WAR for next chunk
    }
}

extern "C" void kernel_launch(void* const* d_in, const int* in_sizes, int n_in,
                              void* d_out, int out_size)
{
    const float* nf    = (const float*)d_in[0];
    const float* ef    = (const float*)d_in[1];
    const float* W     = (const float*)d_in[2];
    const float* bvec  = (const float*)d_in[3];
    const float* scale = (const float*)d_in[4];
    const int*   src   = (const int*)d_in[5];
    const int*   dst   = (const int*)d_in[6];
    float* out = (float*)d_out;

    const int n_nodes = in_sizes[0] / D;
    const int n_edges = in_sizes[5];

    prep_kernel<<<(n_edges + 255) / 256, 256>>>(dst, W, n_nodes, n_edges);
    genconv_kernel<<<1480, 256>>>(nf, ef, bvec, scale, src, out, n_nodes);
}